// round 1
// baseline (speedup 1.0000x reference)
#include <cuda_runtime.h>
#include <math.h>

#define EPS 1e-5f

// ---------------- scratch (device globals; no allocation allowed) ----------------
__device__ float g_bufA[67108864];   // up to 131072 x 512  (also 32768 x 1024)
__device__ float g_bufB[16777216];   // up to 32768 x 512
__device__ float g_bufC[67108864];   // concat buffers: 32768x1024 / 131072x512
__device__ float g_sum[1024];
__device__ float g_sumsq[1024];
__device__ float g_scale[1024];
__device__ float g_shift[1024];

// ---------------- utility kernels ----------------
__global__ void zero_stats_kernel(int n) {
    int i = blockIdx.x * blockDim.x + threadIdx.x;
    if (i < n) { g_sum[i] = 0.f; g_sumsq[i] = 0.f; }
}

// column-wise sum / sumsq over H (M x N), atomically accumulated
__global__ void colstats_kernel(const float* __restrict__ H, int M, int N, int rowsPerBlock) {
    int col = blockIdx.x * blockDim.x + threadIdx.x;
    if (col >= N) return;
    int r0 = blockIdx.y * rowsPerBlock;
    int r1 = r0 + rowsPerBlock; if (r1 > M) r1 = M;
    float s = 0.f, s2 = 0.f;
    for (int r = r0; r < r1; r++) {
        float v = H[(size_t)r * N + col];
        s += v; s2 += v * v;
    }
    atomicAdd(&g_sum[col], s);
    atomicAdd(&g_sumsq[col], s2);
}

__global__ void finalize_stats_kernel(const float* __restrict__ gamma,
                                      const float* __restrict__ beta,
                                      int N, float invM) {
    int i = blockIdx.x * blockDim.x + threadIdx.x;
    if (i >= N) return;
    float mu  = g_sum[i] * invM;
    float var = g_sumsq[i] * invM - mu * mu;
    float sc  = gamma[i] * rsqrtf(var + EPS);
    g_scale[i] = sc;
    g_shift[i] = beta[i] - mu * sc;
}

// out[row, 0:Cl] = left[row], out[row, Cl:Cl+Cr] = right[b*srcRowsPerBatch + idx[row]]
__global__ void build_cat_kernel(const float* __restrict__ left,
                                 const float* __restrict__ right,
                                 const int* __restrict__ idx,
                                 float* __restrict__ out,
                                 int rows, int Cl, int Cr,
                                 int outRowsPerBatch, int srcRowsPerBatch) {
    int cols = Cl + Cr;
    int c4n = cols >> 2;
    long long t = (long long)blockIdx.x * blockDim.x + threadIdx.x;
    long long total = (long long)rows * c4n;
    if (t >= total) return;
    int row = (int)(t / c4n);
    int c4 = (int)(t % c4n) * 4;
    float4 v;
    if (c4 < Cl) {
        v = *(const float4*)(left + (size_t)row * Cl + c4);
    } else {
        int b = row / outRowsPerBatch;
        int src = b * srcRowsPerBatch + idx[row];
        v = *(const float4*)(right + (size_t)src * Cr + (c4 - Cl));
    }
    *(float4*)(out + (size_t)row * cols + c4) = v;
}

// ---------------- GEMM: C = f(A) @ W + bias ----------------
// f(A) = identity            (NORM_RELU = false)
// f(A) = relu(A*scale+shift) (NORM_RELU = true, per-K-column affine)
// BM=BN=128, BK=8, 256 threads, 8x8 per thread. All dims assumed multiples.
template <bool NORM_RELU>
__global__ __launch_bounds__(256, 2)
void gemm_kernel(const float* __restrict__ A, const float* __restrict__ W,
                 const float* __restrict__ bias, float* __restrict__ C,
                 int M, int N, int K) {
    constexpr int BM = 128, BN = 128, BK = 8;
    __shared__ float As[BK][BM];
    __shared__ float Bs[BK][BN];

    const int tid = threadIdx.x;
    const int bx = blockIdx.x;   // along N
    const int by = blockIdx.y;   // along M

    // A tile loads: 128 rows x 8 k = 1024 floats = 256 float4
    const int aRow  = tid >> 1;          // 0..127
    const int aCol4 = (tid & 1) * 4;     // 0 or 4
    // B tile loads: 8 rows x 128 cols = 256 float4
    const int bRow  = tid >> 5;          // 0..7
    const int bCol4 = (tid & 31) * 4;    // 0..124

    const float* Ablk = A + (size_t)by * BM * K;
    const float* Wblk = W + (size_t)bx * BN;
    float* Cblk = C + (size_t)by * BM * N + (size_t)bx * BN;

    const int tr = (tid >> 4) * 8;   // 0..120
    const int tc = (tid & 15) * 8;   // 0..120

    float acc[8][8];
#pragma unroll
    for (int i = 0; i < 8; i++)
#pragma unroll
        for (int j = 0; j < 8; j++) acc[i][j] = 0.f;

    for (int k0 = 0; k0 < K; k0 += BK) {
        float4 av = *(const float4*)(Ablk + (size_t)aRow * K + k0 + aCol4);
        if (NORM_RELU) {
            int kb = k0 + aCol4;
            av.x = fmaxf(av.x * g_scale[kb + 0] + g_shift[kb + 0], 0.f);
            av.y = fmaxf(av.y * g_scale[kb + 1] + g_shift[kb + 1], 0.f);
            av.z = fmaxf(av.z * g_scale[kb + 2] + g_shift[kb + 2], 0.f);
            av.w = fmaxf(av.w * g_scale[kb + 3] + g_shift[kb + 3], 0.f);
        }
        As[aCol4 + 0][aRow] = av.x;
        As[aCol4 + 1][aRow] = av.y;
        As[aCol4 + 2][aRow] = av.z;
        As[aCol4 + 3][aRow] = av.w;

        float4 bv = *(const float4*)(Wblk + (size_t)(k0 + bRow) * N + bCol4);
        *(float4*)&Bs[bRow][bCol4] = bv;

        __syncthreads();

#pragma unroll
        for (int kk = 0; kk < BK; kk++) {
            float ar[8], br[8];
            *(float4*)&ar[0] = *(const float4*)&As[kk][tr];
            *(float4*)&ar[4] = *(const float4*)&As[kk][tr + 4];
            *(float4*)&br[0] = *(const float4*)&Bs[kk][tc];
            *(float4*)&br[4] = *(const float4*)&Bs[kk][tc + 4];
#pragma unroll
            for (int i = 0; i < 8; i++)
#pragma unroll
                for (int j = 0; j < 8; j++)
                    acc[i][j] = fmaf(ar[i], br[j], acc[i][j]);
        }
        __syncthreads();
    }

    float bb[8];
#pragma unroll
    for (int j = 0; j < 8; j++) bb[j] = bias[(size_t)bx * BN + tc + j];

#pragma unroll
    for (int i = 0; i < 8; i++) {
        float4 v0, v1;
        v0.x = acc[i][0] + bb[0]; v0.y = acc[i][1] + bb[1];
        v0.z = acc[i][2] + bb[2]; v0.w = acc[i][3] + bb[3];
        v1.x = acc[i][4] + bb[4]; v1.y = acc[i][5] + bb[5];
        v1.z = acc[i][6] + bb[6]; v1.w = acc[i][7] + bb[7];
        float* crow = Cblk + (size_t)(tr + i) * N + tc;
        *(float4*)(crow)     = v0;
        *(float4*)(crow + 4) = v1;
    }
}

// ---------------- host-side orchestration ----------------
static void run_gemm(const float* A, const float* W, const float* b, float* C,
                     int M, int N, int K, bool norm_relu, cudaStream_t s) {
    dim3 grid(N / 128, M / 128);
    if (norm_relu)
        gemm_kernel<true><<<grid, 256, 0, s>>>(A, W, b, C, M, N, K);
    else
        gemm_kernel<false><<<grid, 256, 0, s>>>(A, W, b, C, M, N, K);
}

static void run_stats(const float* H, int M, int N,
                      const float* g, const float* be, cudaStream_t s) {
    zero_stats_kernel<<<(N + 255) / 256, 256, 0, s>>>(N);
    int rowChunks = 256;
    int rowsPerBlock = (M + rowChunks - 1) / rowChunks;
    dim3 grid((N + 255) / 256, rowChunks);
    colstats_kernel<<<grid, 256, 0, s>>>(H, M, N, rowsPerBlock);
    finalize_stats_kernel<<<(N + 255) / 256, 256, 0, s>>>(g, be, N, 1.0f / (float)M);
}

extern "C" void kernel_launch(void* const* d_in, const int* in_sizes, int n_in,
                              void* d_out, int out_size) {
    const float* f0 = (const float*)d_in[0];
    const float* f1 = (const float*)d_in[1];
    const float* f2 = (const float*)d_in[2];
    const float* up0_w1 = (const float*)d_in[3];
    const float* up0_b1 = (const float*)d_in[4];
    const float* up0_g  = (const float*)d_in[5];
    const float* up0_be = (const float*)d_in[6];
    const float* up0_w2 = (const float*)d_in[7];
    const float* up0_b2 = (const float*)d_in[8];
    const float* up1_w1 = (const float*)d_in[9];
    const float* up1_b1 = (const float*)d_in[10];
    const float* up1_g  = (const float*)d_in[11];
    const float* up1_be = (const float*)d_in[12];
    const float* up1_w2 = (const float*)d_in[13];
    const float* up1_b2 = (const float*)d_in[14];
    const float* skip0_w1 = (const float*)d_in[15];
    const float* skip0_b1 = (const float*)d_in[16];
    const float* skip0_g  = (const float*)d_in[17];
    const float* skip0_be = (const float*)d_in[18];
    const float* skip0_w2 = (const float*)d_in[19];
    const float* skip0_b2 = (const float*)d_in[20];
    const float* skip1_w1 = (const float*)d_in[21];
    const float* skip1_b1 = (const float*)d_in[22];
    const float* skip1_g  = (const float*)d_in[23];
    const float* skip1_be = (const float*)d_in[24];
    const float* skip1_w2 = (const float*)d_in[25];
    const float* skip1_b2 = (const float*)d_in[26];
    const int*   pool0 = (const int*)d_in[27];
    const int*   pool1 = (const int*)d_in[28];
    float* out = (float*)d_out;

    float *bufA, *bufB, *bufC;
    cudaGetSymbolAddress((void**)&bufA, g_bufA);
    cudaGetSymbolAddress((void**)&bufB, g_bufB);
    cudaGetSymbolAddress((void**)&bufC, g_bufC);

    cudaStream_t s = 0;

    const int B = 4;
    const int N0 = 32768, N1 = 8192, N2 = 2048;
    const int C0 = 256, C1 = 512, C2 = 1024;

    // ---- up1 MLP on f2: (B*N2, C2) -> hidden C2 -> C1 ----
    int M_up1 = B * N2;  // 8192
    run_gemm(f2, up1_w1, up1_b1, bufA, M_up1, C2, C2, false, s);
    run_stats(bufA, M_up1, C2, up1_g, up1_be, s);
    run_gemm(bufA, up1_w2, up1_b2, bufB, M_up1, C1, C2, true, s);   // bufB: (8192, 512)

    // ---- gather pool1 + concat with f1 -> bufC (32768, 1024) ----
    {
        int rows = B * N1;  // 32768
        long long total = (long long)rows * ((C1 + C1) / 4);
        int blocks = (int)((total + 255) / 256);
        build_cat_kernel<<<blocks, 256, 0, s>>>(f1, bufB, pool1, bufC,
                                                rows, C1, C1, N1, N2);
    }

    // ---- skip1 MLP: (32768, 1024) -> 1024 -> 512 ----
    int M_s1 = B * N1;  // 32768
    run_gemm(bufC, skip1_w1, skip1_b1, bufA, M_s1, 2 * C1, 2 * C1, false, s);
    run_stats(bufA, M_s1, 2 * C1, skip1_g, skip1_be, s);
    run_gemm(bufA, skip1_w2, skip1_b2, bufB, M_s1, C1, 2 * C1, true, s); // bufB: (32768,512)

    // ---- up0 MLP: (32768, 512) -> 512 -> 256 ----
    run_gemm(bufB, up0_w1, up0_b1, bufA, M_s1, C1, C1, false, s);
    run_stats(bufA, M_s1, C1, up0_g, up0_be, s);
    run_gemm(bufA, up0_w2, up0_b2, bufB, M_s1, C0, C1, true, s);    // bufB: (32768,256)

    // ---- gather pool0 + concat with f0 -> bufC (131072, 512) ----
    {
        int rows = B * N0;  // 131072
        long long total = (long long)rows * ((C0 + C0) / 4);
        int blocks = (int)((total + 255) / 256);
        build_cat_kernel<<<blocks, 256, 0, s>>>(f0, bufB, pool0, bufC,
                                                rows, C0, C0, N0, N1);
    }

    // ---- skip0 MLP: (131072, 512) -> 512 -> 256 -> out ----
    int M_s0 = B * N0;  // 131072
    run_gemm(bufC, skip0_w1, skip0_b1, bufA, M_s0, 2 * C0, 2 * C0, false, s);
    run_stats(bufA, M_s0, 2 * C0, skip0_g, skip0_be, s);
    run_gemm(bufA, skip0_w2, skip0_b2, out, M_s0, C0, 2 * C0, true, s);
}

// round 2
// speedup vs baseline: 1.0009x; 1.0009x over previous
#include <cuda_runtime.h>
#include <math.h>

#define EPS 1e-5f

// ---------------- scratch (device globals; no allocation allowed) ----------------
__device__ float g_bufA[67108864];   // up to 131072 x 512  (also 32768 x 1024)
__device__ float g_bufB[16777216];   // up to 32768 x 512
__device__ float g_bufC[67108864];   // concat buffers: 32768x1024 / 131072x512
__device__ float g_sum[1024];
__device__ float g_sumsq[1024];
__device__ float g_scale[1024];
__device__ float g_shift[1024];

// ---------------- utility kernels ----------------
__global__ void zero_stats_kernel(int n) {
    int i = blockIdx.x * blockDim.x + threadIdx.x;
    if (i < n) { g_sum[i] = 0.f; g_sumsq[i] = 0.f; }
}

// column-wise sum / sumsq over H (M x N), atomically accumulated
__global__ void colstats_kernel(const float* __restrict__ H, int M, int N, int rowsPerBlock) {
    int col = blockIdx.x * blockDim.x + threadIdx.x;
    if (col >= N) return;
    int r0 = blockIdx.y * rowsPerBlock;
    int r1 = r0 + rowsPerBlock; if (r1 > M) r1 = M;
    float s = 0.f, s2 = 0.f;
    for (int r = r0; r < r1; r++) {
        float v = H[(size_t)r * N + col];
        s += v; s2 += v * v;
    }
    atomicAdd(&g_sum[col], s);
    atomicAdd(&g_sumsq[col], s2);
}

__global__ void finalize_stats_kernel(const float* __restrict__ gamma,
                                      const float* __restrict__ beta,
                                      int N, float invM) {
    int i = blockIdx.x * blockDim.x + threadIdx.x;
    if (i >= N) return;
    float mu  = g_sum[i] * invM;
    float var = g_sumsq[i] * invM - mu * mu;
    float sc  = gamma[i] * rsqrtf(var + EPS);
    g_scale[i] = sc;
    g_shift[i] = beta[i] - mu * sc;
}

// out[row, 0:Cl] = left[row], out[row, Cl:Cl+Cr] = right[b*srcRowsPerBatch + idx[row]]
__global__ void build_cat_kernel(const float* __restrict__ left,
                                 const float* __restrict__ right,
                                 const int* __restrict__ idx,
                                 float* __restrict__ out,
                                 int rows, int Cl, int Cr,
                                 int outRowsPerBatch, int srcRowsPerBatch) {
    int cols = Cl + Cr;
    int c4n = cols >> 2;
    long long t = (long long)blockIdx.x * blockDim.x + threadIdx.x;
    long long total = (long long)rows * c4n;
    if (t >= total) return;
    int row = (int)(t / c4n);
    int c4 = (int)(t % c4n) * 4;
    float4 v;
    if (c4 < Cl) {
        v = *(const float4*)(left + (size_t)row * Cl + c4);
    } else {
        int b = row / outRowsPerBatch;
        int src = b * srcRowsPerBatch + idx[row];
        v = *(const float4*)(right + (size_t)src * Cr + (c4 - Cl));
    }
    *(float4*)(out + (size_t)row * cols + c4) = v;
}

// ---------------- GEMM: C = f(A) @ W + bias ----------------
// f(A) = identity            (NORM_RELU = false)
// f(A) = relu(A*scale+shift) (NORM_RELU = true, per-K-column affine)
// BM=BN=128, BK=8, 256 threads, 8x8 per thread. All dims assumed multiples.
template <bool NORM_RELU>
__global__ __launch_bounds__(256, 2)
void gemm_kernel(const float* __restrict__ A, const float* __restrict__ W,
                 const float* __restrict__ bias, float* __restrict__ C,
                 int M, int N, int K) {
    constexpr int BM = 128, BN = 128, BK = 8;
    __shared__ float As[BK][BM];
    __shared__ float Bs[BK][BN];

    const int tid = threadIdx.x;
    const int bx = blockIdx.x;   // along N
    const int by = blockIdx.y;   // along M

    // A tile loads: 128 rows x 8 k = 1024 floats = 256 float4
    const int aRow  = tid >> 1;          // 0..127
    const int aCol4 = (tid & 1) * 4;     // 0 or 4
    // B tile loads: 8 rows x 128 cols = 256 float4
    const int bRow  = tid >> 5;          // 0..7
    const int bCol4 = (tid & 31) * 4;    // 0..124

    const float* Ablk = A + (size_t)by * BM * K;
    const float* Wblk = W + (size_t)bx * BN;
    float* Cblk = C + (size_t)by * BM * N + (size_t)bx * BN;

    const int tr = (tid >> 4) * 8;   // 0..120
    const int tc = (tid & 15) * 8;   // 0..120

    float acc[8][8];
#pragma unroll
    for (int i = 0; i < 8; i++)
#pragma unroll
        for (int j = 0; j < 8; j++) acc[i][j] = 0.f;

    for (int k0 = 0; k0 < K; k0 += BK) {
        float4 av = *(const float4*)(Ablk + (size_t)aRow * K + k0 + aCol4);
        if (NORM_RELU) {
            int kb = k0 + aCol4;
            av.x = fmaxf(av.x * g_scale[kb + 0] + g_shift[kb + 0], 0.f);
            av.y = fmaxf(av.y * g_scale[kb + 1] + g_shift[kb + 1], 0.f);
            av.z = fmaxf(av.z * g_scale[kb + 2] + g_shift[kb + 2], 0.f);
            av.w = fmaxf(av.w * g_scale[kb + 3] + g_shift[kb + 3], 0.f);
        }
        As[aCol4 + 0][aRow] = av.x;
        As[aCol4 + 1][aRow] = av.y;
        As[aCol4 + 2][aRow] = av.z;
        As[aCol4 + 3][aRow] = av.w;

        float4 bv = *(const float4*)(Wblk + (size_t)(k0 + bRow) * N + bCol4);
        *(float4*)&Bs[bRow][bCol4] = bv;

        __syncthreads();

#pragma unroll
        for (int kk = 0; kk < BK; kk++) {
            float ar[8], br[8];
            *(float4*)&ar[0] = *(const float4*)&As[kk][tr];
            *(float4*)&ar[4] = *(const float4*)&As[kk][tr + 4];
            *(float4*)&br[0] = *(const float4*)&Bs[kk][tc];
            *(float4*)&br[4] = *(const float4*)&Bs[kk][tc + 4];
#pragma unroll
            for (int i = 0; i < 8; i++)
#pragma unroll
                for (int j = 0; j < 8; j++)
                    acc[i][j] = fmaf(ar[i], br[j], acc[i][j]);
        }
        __syncthreads();
    }

    float bb[8];
#pragma unroll
    for (int j = 0; j < 8; j++) bb[j] = bias[(size_t)bx * BN + tc + j];

#pragma unroll
    for (int i = 0; i < 8; i++) {
        float4 v0, v1;
        v0.x = acc[i][0] + bb[0]; v0.y = acc[i][1] + bb[1];
        v0.z = acc[i][2] + bb[2]; v0.w = acc[i][3] + bb[3];
        v1.x = acc[i][4] + bb[4]; v1.y = acc[i][5] + bb[5];
        v1.z = acc[i][6] + bb[6]; v1.w = acc[i][7] + bb[7];
        float* crow = Cblk + (size_t)(tr + i) * N + tc;
        *(float4*)(crow)     = v0;
        *(float4*)(crow + 4) = v1;
    }
}

// ---------------- host-side orchestration ----------------
static void run_gemm(const float* A, const float* W, const float* b, float* C,
                     int M, int N, int K, bool norm_relu, cudaStream_t s) {
    dim3 grid(N / 128, M / 128);
    if (norm_relu)
        gemm_kernel<true><<<grid, 256, 0, s>>>(A, W, b, C, M, N, K);
    else
        gemm_kernel<false><<<grid, 256, 0, s>>>(A, W, b, C, M, N, K);
}

static void run_stats(const float* H, int M, int N,
                      const float* g, const float* be, cudaStream_t s) {
    zero_stats_kernel<<<(N + 255) / 256, 256, 0, s>>>(N);
    int rowChunks = 256;
    int rowsPerBlock = (M + rowChunks - 1) / rowChunks;
    dim3 grid((N + 255) / 256, rowChunks);
    colstats_kernel<<<grid, 256, 0, s>>>(H, M, N, rowsPerBlock);
    finalize_stats_kernel<<<(N + 255) / 256, 256, 0, s>>>(g, be, N, 1.0f / (float)M);
}

extern "C" void kernel_launch(void* const* d_in, const int* in_sizes, int n_in,
                              void* d_out, int out_size) {
    const float* f0 = (const float*)d_in[0];
    const float* f1 = (const float*)d_in[1];
    const float* f2 = (const float*)d_in[2];
    const float* up0_w1 = (const float*)d_in[3];
    const float* up0_b1 = (const float*)d_in[4];
    const float* up0_g  = (const float*)d_in[5];
    const float* up0_be = (const float*)d_in[6];
    const float* up0_w2 = (const float*)d_in[7];
    const float* up0_b2 = (const float*)d_in[8];
    const float* up1_w1 = (const float*)d_in[9];
    const float* up1_b1 = (const float*)d_in[10];
    const float* up1_g  = (const float*)d_in[11];
    const float* up1_be = (const float*)d_in[12];
    const float* up1_w2 = (const float*)d_in[13];
    const float* up1_b2 = (const float*)d_in[14];
    const float* skip0_w1 = (const float*)d_in[15];
    const float* skip0_b1 = (const float*)d_in[16];
    const float* skip0_g  = (const float*)d_in[17];
    const float* skip0_be = (const float*)d_in[18];
    const float* skip0_w2 = (const float*)d_in[19];
    const float* skip0_b2 = (const float*)d_in[20];
    const float* skip1_w1 = (const float*)d_in[21];
    const float* skip1_b1 = (const float*)d_in[22];
    const float* skip1_g  = (const float*)d_in[23];
    const float* skip1_be = (const float*)d_in[24];
    const float* skip1_w2 = (const float*)d_in[25];
    const float* skip1_b2 = (const float*)d_in[26];
    const int*   pool0 = (const int*)d_in[27];
    const int*   pool1 = (const int*)d_in[28];
    float* out = (float*)d_out;

    float *bufA, *bufB, *bufC;
    cudaGetSymbolAddress((void**)&bufA, g_bufA);
    cudaGetSymbolAddress((void**)&bufB, g_bufB);
    cudaGetSymbolAddress((void**)&bufC, g_bufC);

    cudaStream_t s = 0;

    const int B = 4;
    const int N0 = 32768, N1 = 8192, N2 = 2048;
    const int C0 = 256, C1 = 512, C2 = 1024;

    // ---- up1 MLP on f2: (B*N2, C2) -> hidden C2 -> C1 ----
    int M_up1 = B * N2;  // 8192
    run_gemm(f2, up1_w1, up1_b1, bufA, M_up1, C2, C2, false, s);
    run_stats(bufA, M_up1, C2, up1_g, up1_be, s);
    run_gemm(bufA, up1_w2, up1_b2, bufB, M_up1, C1, C2, true, s);   // bufB: (8192, 512)

    // ---- gather pool1 + concat with f1 -> bufC (32768, 1024) ----
    {
        int rows = B * N1;  // 32768
        long long total = (long long)rows * ((C1 + C1) / 4);
        int blocks = (int)((total + 255) / 256);
        build_cat_kernel<<<blocks, 256, 0, s>>>(f1, bufB, pool1, bufC,
                                                rows, C1, C1, N1, N2);
    }

    // ---- skip1 MLP: (32768, 1024) -> 1024 -> 512 ----
    int M_s1 = B * N1;  // 32768
    run_gemm(bufC, skip1_w1, skip1_b1, bufA, M_s1, 2 * C1, 2 * C1, false, s);
    run_stats(bufA, M_s1, 2 * C1, skip1_g, skip1_be, s);
    run_gemm(bufA, skip1_w2, skip1_b2, bufB, M_s1, C1, 2 * C1, true, s); // bufB: (32768,512)

    // ---- up0 MLP: (32768, 512) -> 512 -> 256 ----
    run_gemm(bufB, up0_w1, up0_b1, bufA, M_s1, C1, C1, false, s);
    run_stats(bufA, M_s1, C1, up0_g, up0_be, s);
    run_gemm(bufA, up0_w2, up0_b2, bufB, M_s1, C0, C1, true, s);    // bufB: (32768,256)

    // ---- gather pool0 + concat with f0 -> bufC (131072, 512) ----
    {
        int rows = B * N0;  // 131072
        long long total = (long long)rows * ((C0 + C0) / 4);
        int blocks = (int)((total + 255) / 256);
        build_cat_kernel<<<blocks, 256, 0, s>>>(f0, bufB, pool0, bufC,
                                                rows, C0, C0, N0, N1);
    }

    // ---- skip0 MLP: (131072, 512) -> 512 -> 256 -> out ----
    int M_s0 = B * N0;  // 131072
    run_gemm(bufC, skip0_w1, skip0_b1, bufA, M_s0, 2 * C0, 2 * C0, false, s);
    run_stats(bufA, M_s0, 2 * C0, skip0_g, skip0_be, s);
    run_gemm(bufA, skip0_w2, skip0_b2, out, M_s0, C0, 2 * C0, true, s);
}

// round 4
// speedup vs baseline: 2.4985x; 2.4963x over previous
#include <cuda_runtime.h>
#include <cuda_bf16.h>
#include <cstdint>
#include <math.h>

#define EPS 1e-5f

// ---------------- scratch (device globals; no allocation allowed) ----------------
__device__ float g_bufA[67108864];   // up to 131072 x 512  (also 32768 x 1024)
__device__ float g_bufB[16777216];   // up to 32768 x 512
__device__ float g_bufC[67108864];   // concat buffers
__device__ float g_sum[1024];
__device__ float g_sumsq[1024];
__device__ float g_scale[1024];
__device__ float g_shift[1024];

// ---------------- utility kernels ----------------
__global__ void zero_stats_kernel(int n) {
    int i = blockIdx.x * blockDim.x + threadIdx.x;
    if (i < n) { g_sum[i] = 0.f; g_sumsq[i] = 0.f; }
}

__global__ void colstats_kernel(const float* __restrict__ H, int M, int N, int rowsPerBlock) {
    int col = blockIdx.x * blockDim.x + threadIdx.x;
    if (col >= N) return;
    int r0 = blockIdx.y * rowsPerBlock;
    int r1 = r0 + rowsPerBlock; if (r1 > M) r1 = M;
    float s = 0.f, s2 = 0.f;
    for (int r = r0; r < r1; r++) {
        float v = H[(size_t)r * N + col];
        s += v; s2 += v * v;
    }
    atomicAdd(&g_sum[col], s);
    atomicAdd(&g_sumsq[col], s2);
}

__global__ void finalize_stats_kernel(const float* __restrict__ gamma,
                                      const float* __restrict__ beta,
                                      int N, float invM) {
    int i = blockIdx.x * blockDim.x + threadIdx.x;
    if (i >= N) return;
    float mu  = g_sum[i] * invM;
    float var = g_sumsq[i] * invM - mu * mu;
    float sc  = gamma[i] * rsqrtf(var + EPS);
    g_scale[i] = sc;
    g_shift[i] = beta[i] - mu * sc;
}

__global__ void build_cat_kernel(const float* __restrict__ left,
                                 const float* __restrict__ right,
                                 const int* __restrict__ idx,
                                 float* __restrict__ out,
                                 int rows, int Cl, int Cr,
                                 int outRowsPerBatch, int srcRowsPerBatch) {
    int cols = Cl + Cr;
    int c4n = cols >> 2;
    long long t = (long long)blockIdx.x * blockDim.x + threadIdx.x;
    long long total = (long long)rows * c4n;
    if (t >= total) return;
    int row = (int)(t / c4n);
    int c4 = (int)(t % c4n) * 4;
    float4 v;
    if (c4 < Cl) {
        v = *(const float4*)(left + (size_t)row * Cl + c4);
    } else {
        int b = row / outRowsPerBatch;
        int src = b * srcRowsPerBatch + idx[row];
        v = *(const float4*)(right + (size_t)src * Cr + (c4 - Cl));
    }
    *(float4*)(out + (size_t)row * cols + c4) = v;
}

// ---------------- HMMA GEMM core ----------------
__device__ __forceinline__ uint32_t smem_u32(const void* p) {
    uint32_t a;
    asm("{ .reg .u64 t; cvta.to.shared.u64 t, %1; cvt.u32.u64 %0, t; }" : "=r"(a) : "l"(p));
    return a;
}

__device__ __forceinline__ void ldsm_x4(uint32_t* r, uint32_t addr) {
    asm volatile("ldmatrix.sync.aligned.m8n8.x4.shared.b16 {%0,%1,%2,%3}, [%4];"
                 : "=r"(r[0]), "=r"(r[1]), "=r"(r[2]), "=r"(r[3]) : "r"(addr));
}
__device__ __forceinline__ void ldsm_x4_t(uint32_t* r, uint32_t addr) {
    asm volatile("ldmatrix.sync.aligned.m8n8.x4.trans.shared.b16 {%0,%1,%2,%3}, [%4];"
                 : "=r"(r[0]), "=r"(r[1]), "=r"(r[2]), "=r"(r[3]) : "r"(addr));
}
__device__ __forceinline__ void mma16816(float* d, const uint32_t* a, uint32_t b0, uint32_t b1) {
    asm volatile("mma.sync.aligned.m16n8k16.row.col.f32.bf16.bf16.f32 "
                 "{%0,%1,%2,%3}, {%4,%5,%6,%7}, {%8,%9}, {%0,%1,%2,%3};"
                 : "+f"(d[0]), "+f"(d[1]), "+f"(d[2]), "+f"(d[3])
                 : "r"(a[0]), "r"(a[1]), "r"(a[2]), "r"(a[3]), "r"(b0), "r"(b1));
}

// fp32x4 -> hi/lo bf16x4 written as 8B each
__device__ __forceinline__ void split4s(float4 v, char* hp, char* lp) {
    __nv_bfloat162 h01 = __floats2bfloat162_rn(v.x, v.y);
    __nv_bfloat162 h23 = __floats2bfloat162_rn(v.z, v.w);
    float2 f01 = __bfloat1622float2(h01);
    float2 f23 = __bfloat1622float2(h23);
    __nv_bfloat162 l01 = __floats2bfloat162_rn(v.x - f01.x, v.y - f01.y);
    __nv_bfloat162 l23 = __floats2bfloat162_rn(v.z - f23.x, v.w - f23.y);
    uint2 hv, lv;
    hv.x = *reinterpret_cast<uint32_t*>(&h01);
    hv.y = *reinterpret_cast<uint32_t*>(&h23);
    lv.x = *reinterpret_cast<uint32_t*>(&l01);
    lv.y = *reinterpret_cast<uint32_t*>(&l23);
    *reinterpret_cast<uint2*>(hp) = hv;
    *reinterpret_cast<uint2*>(lp) = lv;
}

// C = f(A) @ W + bias.  A (M,K) fp32 row-major; W (K,N) fp32 row-major.
// f = identity or BN-normalize+ReLU (per-K-column scale/shift from g_scale/g_shift).
// BM=128, BN=128, BK=32; split-bf16 3-product HMMA.
template <bool NORM_RELU>
__global__ __launch_bounds__(256, 1)
void hmma_gemm_kernel(const float* __restrict__ A, const float* __restrict__ W,
                      const float* __restrict__ bias, float* __restrict__ C,
                      int M, int N, int K) {
    constexpr int A_STR = 80;     // bytes per A smem row (32 bf16 + pad)
    constexpr int W_STR = 272;    // bytes per W smem row (128 bf16 + pad)
    constexpr int A_PLANE = 128 * A_STR;            // 10240
    constexpr int W_PLANE = 32 * W_STR;             // 8704
    constexpr int OFF_AH = 0;
    constexpr int OFF_AL = A_PLANE;
    constexpr int OFF_WH = 2 * A_PLANE;
    constexpr int OFF_WL = 2 * A_PLANE + W_PLANE;
    constexpr int STAGE = 2 * A_PLANE + 2 * W_PLANE;  // 37888

    extern __shared__ char sm[];
    const uint32_t smb = smem_u32(sm);

    const int tid = threadIdx.x;
    const int wid = tid >> 5;
    const int lane = tid & 31;
    const int warp_m = (wid >> 2) * 64;     // 0 or 64
    const int warp_n = (wid & 3) * 32;      // 0,32,64,96
    const int bm0 = blockIdx.y * 128;
    const int bn0 = blockIdx.x * 128;
    const int T = K >> 5;

    // global load mapping
    int a_row[4], a_c[4], w_row[4], w_c[4];
    uint32_t a_soff[4], w_soff[4];
#pragma unroll
    for (int i = 0; i < 4; i++) {
        int idx = tid + (i << 8);
        a_row[i] = idx >> 3;            a_c[i] = (idx & 7) << 2;
        w_row[i] = idx >> 5;            w_c[i] = (idx & 31) << 2;
        a_soff[i] = a_row[i] * A_STR + a_c[i] * 2;
        w_soff[i] = w_row[i] * W_STR + w_c[i] * 2;
    }

    // ldmatrix fragment addresses (stage-relative)
    uint32_t a_off[4], b_off[2];
#pragma unroll
    for (int mt = 0; mt < 4; mt++)
        a_off[mt] = (uint32_t)((warp_m + mt * 16 + (lane & 15)) * A_STR + ((lane >> 4) << 3) * 2);
#pragma unroll
    for (int np = 0; np < 2; np++)
        b_off[np] = (uint32_t)((lane & 15) * W_STR + (warp_n + np * 16 + ((lane >> 4) << 3)) * 2);

    float acc[4][4][4];
#pragma unroll
    for (int mt = 0; mt < 4; mt++)
#pragma unroll
        for (int nt = 0; nt < 4; nt++)
#pragma unroll
            for (int q = 0; q < 4; q++) acc[mt][nt][q] = 0.f;

    float4 ar[4], wr[4], scv[4], shv[4];

    // preload tile 0
#pragma unroll
    for (int i = 0; i < 4; i++) {
        ar[i] = *(const float4*)(A + (size_t)(bm0 + a_row[i]) * K + a_c[i]);
        wr[i] = *(const float4*)(W + (size_t)w_row[i] * N + bn0 + w_c[i]);
        if (NORM_RELU) {
            scv[i] = *(const float4*)(g_scale + a_c[i]);
            shv[i] = *(const float4*)(g_shift + a_c[i]);
        }
    }
#pragma unroll
    for (int i = 0; i < 4; i++) {
        float4 v = ar[i];
        if (NORM_RELU) {
            v.x = fmaxf(v.x * scv[i].x + shv[i].x, 0.f);
            v.y = fmaxf(v.y * scv[i].y + shv[i].y, 0.f);
            v.z = fmaxf(v.z * scv[i].z + shv[i].z, 0.f);
            v.w = fmaxf(v.w * scv[i].w + shv[i].w, 0.f);
        }
        split4s(v, sm + OFF_AH + a_soff[i], sm + OFF_AL + a_soff[i]);
        split4s(wr[i], sm + OFF_WH + w_soff[i], sm + OFF_WL + w_soff[i]);
    }
    __syncthreads();

    for (int t = 0; t < T; t++) {
        const int s = t & 1;
        const uint32_t sbase = smb + s * STAGE;
        const int has_next = (t + 1 < T);

        if (has_next) {
            const int k0 = (t + 1) << 5;
#pragma unroll
            for (int i = 0; i < 4; i++) {
                ar[i] = *(const float4*)(A + (size_t)(bm0 + a_row[i]) * K + k0 + a_c[i]);
                wr[i] = *(const float4*)(W + (size_t)(k0 + w_row[i]) * N + bn0 + w_c[i]);
                if (NORM_RELU) {
                    scv[i] = *(const float4*)(g_scale + k0 + a_c[i]);
                    shv[i] = *(const float4*)(g_shift + k0 + a_c[i]);
                }
            }
        }

#pragma unroll
        for (int ks = 0; ks < 2; ks++) {
            uint32_t ah[4][4], al[4][4], bh[2][4], bl[2][4];
#pragma unroll
            for (int mt = 0; mt < 4; mt++) {
                ldsm_x4(ah[mt], sbase + OFF_AH + a_off[mt] + ks * 32);
                ldsm_x4(al[mt], sbase + OFF_AL + a_off[mt] + ks * 32);
            }
#pragma unroll
            for (int np = 0; np < 2; np++) {
                ldsm_x4_t(bh[np], sbase + OFF_WH + b_off[np] + ks * (16 * W_STR));
                ldsm_x4_t(bl[np], sbase + OFF_WL + b_off[np] + ks * (16 * W_STR));
            }
#pragma unroll
            for (int mt = 0; mt < 4; mt++) {
#pragma unroll
                for (int nt = 0; nt < 4; nt++) {
                    const uint32_t* bhp = &bh[nt >> 1][(nt & 1) * 2];
                    const uint32_t* blp = &bl[nt >> 1][(nt & 1) * 2];
                    mma16816(acc[mt][nt], ah[mt], bhp[0], bhp[1]);
                    mma16816(acc[mt][nt], ah[mt], blp[0], blp[1]);
                    mma16816(acc[mt][nt], al[mt], bhp[0], bhp[1]);
                }
            }
        }

        if (has_next) {
            char* nb = sm + (s ^ 1) * STAGE;
#pragma unroll
            for (int i = 0; i < 4; i++) {
                float4 v = ar[i];
                if (NORM_RELU) {
                    v.x = fmaxf(v.x * scv[i].x + shv[i].x, 0.f);
                    v.y = fmaxf(v.y * scv[i].y + shv[i].y, 0.f);
                    v.z = fmaxf(v.z * scv[i].z + shv[i].z, 0.f);
                    v.w = fmaxf(v.w * scv[i].w + shv[i].w, 0.f);
                }
                split4s(v, nb + OFF_AH + a_soff[i], nb + OFF_AL + a_soff[i]);
                split4s(wr[i], nb + OFF_WH + w_soff[i], nb + OFF_WL + w_soff[i]);
            }
        }
        __syncthreads();
    }

    // epilogue: bias + store
#pragma unroll
    for (int mt = 0; mt < 4; mt++) {
#pragma unroll
        for (int nt = 0; nt < 4; nt++) {
            int r0 = bm0 + warp_m + mt * 16 + (lane >> 2);
            int c0 = bn0 + warp_n + nt * 8 + (lane & 3) * 2;
            float b0 = bias[c0], b1 = bias[c0 + 1];
            float2 v0, v1;
            v0.x = acc[mt][nt][0] + b0; v0.y = acc[mt][nt][1] + b1;
            v1.x = acc[mt][nt][2] + b0; v1.y = acc[mt][nt][3] + b1;
            *(float2*)(C + (size_t)r0 * N + c0) = v0;
            *(float2*)(C + (size_t)(r0 + 8) * N + c0) = v1;
        }
    }
}

// ---------------- host-side orchestration ----------------
static const int GEMM_SMEM = 2 * 37888;   // 75776

static void run_gemm(const float* A, const float* W, const float* b, float* C,
                     int M, int N, int K, bool norm_relu) {
    dim3 grid(N / 128, M / 128);
    if (norm_relu)
        hmma_gemm_kernel<true><<<grid, 256, GEMM_SMEM>>>(A, W, b, C, M, N, K);
    else
        hmma_gemm_kernel<false><<<grid, 256, GEMM_SMEM>>>(A, W, b, C, M, N, K);
}

static void run_stats(const float* H, int M, int N, const float* g, const float* be) {
    zero_stats_kernel<<<(N + 255) / 256, 256>>>(N);
    int rowChunks = 256;
    int rowsPerBlock = (M + rowChunks - 1) / rowChunks;
    dim3 grid((N + 255) / 256, rowChunks);
    colstats_kernel<<<grid, 256>>>(H, M, N, rowsPerBlock);
    finalize_stats_kernel<<<(N + 255) / 256, 256>>>(g, be, N, 1.0f / (float)M);
}

extern "C" void kernel_launch(void* const* d_in, const int* in_sizes, int n_in,
                              void* d_out, int out_size) {
    const float* f0 = (const float*)d_in[0];
    const float* f1 = (const float*)d_in[1];
    const float* f2 = (const float*)d_in[2];
    const float* up0_w1 = (const float*)d_in[3];
    const float* up0_b1 = (const float*)d_in[4];
    const float* up0_g  = (const float*)d_in[5];
    const float* up0_be = (const float*)d_in[6];
    const float* up0_w2 = (const float*)d_in[7];
    const float* up0_b2 = (const float*)d_in[8];
    const float* up1_w1 = (const float*)d_in[9];
    const float* up1_b1 = (const float*)d_in[10];
    const float* up1_g  = (const float*)d_in[11];
    const float* up1_be = (const float*)d_in[12];
    const float* up1_w2 = (const float*)d_in[13];
    const float* up1_b2 = (const float*)d_in[14];
    const float* skip0_w1 = (const float*)d_in[15];
    const float* skip0_b1 = (const float*)d_in[16];
    const float* skip0_g  = (const float*)d_in[17];
    const float* skip0_be = (const float*)d_in[18];
    const float* skip0_w2 = (const float*)d_in[19];
    const float* skip0_b2 = (const float*)d_in[20];
    const float* skip1_w1 = (const float*)d_in[21];
    const float* skip1_b1 = (const float*)d_in[22];
    const float* skip1_g  = (const float*)d_in[23];
    const float* skip1_be = (const float*)d_in[24];
    const float* skip1_w2 = (const float*)d_in[25];
    const float* skip1_b2 = (const float*)d_in[26];
    const int*   pool0 = (const int*)d_in[27];
    const int*   pool1 = (const int*)d_in[28];
    float* out = (float*)d_out;

    float *bufA, *bufB, *bufC;
    cudaGetSymbolAddress((void**)&bufA, g_bufA);
    cudaGetSymbolAddress((void**)&bufB, g_bufB);
    cudaGetSymbolAddress((void**)&bufC, g_bufC);

    cudaFuncSetAttribute(hmma_gemm_kernel<false>, cudaFuncAttributeMaxDynamicSharedMemorySize, GEMM_SMEM);
    cudaFuncSetAttribute(hmma_gemm_kernel<true>,  cudaFuncAttributeMaxDynamicSharedMemorySize, GEMM_SMEM);

    const int B = 4;
    const int N0 = 32768, N1 = 8192, N2 = 2048;
    const int C0 = 256, C1 = 512, C2 = 1024;

    // ---- up1 MLP on f2: (8192, 1024) -> 1024 -> 512 ----
    int M_u1 = B * N2;
    run_gemm(f2, up1_w1, up1_b1, bufA, M_u1, C2, C2, false);
    run_stats(bufA, M_u1, C2, up1_g, up1_be);
    run_gemm(bufA, up1_w2, up1_b2, bufB, M_u1, C1, C2, true);

    // ---- gather pool1 + concat f1 -> bufC (32768, 1024) ----
    int M_s1 = B * N1;
    {
        long long total = (long long)M_s1 * ((2 * C1) / 4);
        build_cat_kernel<<<(int)((total + 255) / 256), 256>>>(f1, bufB, pool1, bufC,
                                                              M_s1, C1, C1, N1, N2);
    }

    // ---- skip1 MLP: (32768, 1024) -> 1024 -> 512 ----
    run_gemm(bufC, skip1_w1, skip1_b1, bufA, M_s1, 2 * C1, 2 * C1, false);
    run_stats(bufA, M_s1, 2 * C1, skip1_g, skip1_be);
    run_gemm(bufA, skip1_w2, skip1_b2, bufB, M_s1, C1, 2 * C1, true);

    // ---- up0 MLP: (32768, 512) -> 512 -> 256 ----
    run_gemm(bufB, up0_w1, up0_b1, bufA, M_s1, C1, C1, false);
    run_stats(bufA, M_s1, C1, up0_g, up0_be);
    run_gemm(bufA, up0_w2, up0_b2, bufB, M_s1, C0, C1, true);

    // ---- gather pool0 + concat f0 -> bufC (131072, 512) ----
    int M_s0 = B * N0;
    {
        long long total = (long long)M_s0 * ((2 * C0) / 4);
        build_cat_kernel<<<(int)((total + 255) / 256), 256>>>(f0, bufB, pool0, bufC,
                                                              M_s0, C0, C0, N0, N1);
    }

    // ---- skip0 MLP: (131072, 512) -> 512 -> 256 -> out ----
    run_gemm(bufC, skip0_w1, skip0_b1, bufA, M_s0, 2 * C0, 2 * C0, false);
    run_stats(bufA, M_s0, 2 * C0, skip0_g, skip0_be);
    run_gemm(bufA, skip0_w2, skip0_b2, out, M_s0, C0, 2 * C0, true);
}